// round 4
// baseline (speedup 1.0000x reference)
#include <cuda_runtime.h>
#include <cuda_bf16.h>

#define N_NODES 600000
#define N_EDGES 2400000
#define LEADS 12
#define NUM_GRAPHS 50000
#define F_IN 128
#define HDIM 64
#define OUT_DIM 32

#define SCAN_NB 586   // ceil(600000/1024)

// ---------------- packed fp32x2 FMA -------------------------------------------
__device__ __forceinline__ void fma2(unsigned long long& d,
                                     unsigned long long a,
                                     unsigned long long b) {
    asm("fma.rn.f32x2 %0, %1, %2, %0;" : "+l"(d) : "l"(a), "l"(b));
}
__device__ __forceinline__ float hsum2(unsigned long long d) {
    float lo = __uint_as_float((unsigned int)(d & 0xffffffffULL));
    float hi = __uint_as_float((unsigned int)(d >> 32));
    return lo + hi;
}

// ---------------- scratch (device globals) ------------------------------------
__device__ float g_h [(size_t)N_NODES * HDIM];   // ping
__device__ float g_h2[(size_t)N_NODES * HDIM];   // pong
__device__ float g_dinv[N_NODES];
__device__ int   g_deg[N_NODES];
__device__ int   g_rowoff[N_NODES + 1];
__device__ int   g_cursor[N_NODES];
__device__ int   g_csr[N_EDGES];
__device__ int   g_bsum[SCAN_NB];
__device__ int   g_boff[SCAN_NB];

// ---------------- degree / CSR build -------------------------------------------
__global__ void k_deg_zero() {
    int i = blockIdx.x * blockDim.x + threadIdx.x;
    if (i < N_NODES) g_deg[i] = 0;
}

__global__ void k_deg_count(const int* __restrict__ dst) {
    int e = blockIdx.x * blockDim.x + threadIdx.x;
    if (e < N_EDGES) atomicAdd(&g_deg[dst[e]], 1);
}

__global__ void k_dinv() {
    int i = blockIdx.x * blockDim.x + threadIdx.x;
    if (i < N_NODES) g_dinv[i] = rsqrtf((float)(g_deg[i] + 1));
}

__global__ void k_scan1() {
    __shared__ int sh[1024];
    int i = blockIdx.x * 1024 + threadIdx.x;
    int v = (i < N_NODES) ? g_deg[i] : 0;
    sh[threadIdx.x] = v;
    __syncthreads();
    #pragma unroll
    for (int off = 1; off < 1024; off <<= 1) {
        int t = 0;
        if (threadIdx.x >= off) t = sh[threadIdx.x - off];
        __syncthreads();
        if (threadIdx.x >= off) sh[threadIdx.x] += t;
        __syncthreads();
    }
    if (i < N_NODES) g_rowoff[i] = sh[threadIdx.x] - v;   // exclusive
    if (threadIdx.x == 1023) g_bsum[blockIdx.x] = sh[1023];
}

__global__ void k_scan2() {
    __shared__ int sh[1024];
    int v = (threadIdx.x < SCAN_NB) ? g_bsum[threadIdx.x] : 0;
    sh[threadIdx.x] = v;
    __syncthreads();
    #pragma unroll
    for (int off = 1; off < 1024; off <<= 1) {
        int t = 0;
        if (threadIdx.x >= off) t = sh[threadIdx.x - off];
        __syncthreads();
        if (threadIdx.x >= off) sh[threadIdx.x] += t;
        __syncthreads();
    }
    if (threadIdx.x < SCAN_NB) g_boff[threadIdx.x] = sh[threadIdx.x] - v;
}

__global__ void k_scan3() {
    int i = blockIdx.x * blockDim.x + threadIdx.x;
    if (i < N_NODES) {
        int ro = g_rowoff[i] + g_boff[i >> 10];
        g_rowoff[i] = ro;
        g_cursor[i] = ro;
    }
    if (i == 0) g_rowoff[N_NODES] = N_EDGES;
}

__global__ void k_place(const int* __restrict__ src, const int* __restrict__ dst) {
    int e = blockIdx.x * blockDim.x + threadIdx.x;
    if (e < N_EDGES) {
        int pos = atomicAdd(&g_cursor[dst[e]], 1);
        g_csr[pos] = src[e];
    }
}

// ---------------- GEMM layer 1: C = (x @ W1) * dinv[row] -----------------------
__global__ void k_gemm1(const float* __restrict__ A, const float* __restrict__ W,
                        float* __restrict__ C) {
    constexpr int K = 128, BM = 128, KQ = K / 4, KP = K + 4;
    extern __shared__ float smem[];
    float* sA  = smem;            // [BM][K]
    float* sWt = smem + BM * K;   // [64][K+4]

    const int tid = threadIdx.x;
    const int r0 = blockIdx.x * BM;

    for (int i = tid; i < K * 64; i += 256) {
        int k = i >> 6, c = i & 63;
        sWt[c * KP + k] = W[i];
    }
    const float4* A4 = (const float4*)A;
    float4* sA4 = (float4*)sA;
    for (int i = tid; i < BM * KQ; i += 256) {
        int row = i / KQ, kq = i - row * KQ;
        float4 a = make_float4(0.f, 0.f, 0.f, 0.f);
        if (r0 + row < N_NODES) a = A4[(size_t)(r0 + row) * KQ + kq];
        sA4[i] = a;
    }
    __syncthreads();

    const int ci = tid & 15;
    const int ri = tid >> 4;
    unsigned long long acc[8][4];
    #pragma unroll
    for (int j = 0; j < 8; j++)
        #pragma unroll
        for (int c = 0; c < 4; c++) acc[j][c] = 0ULL;

    const float* wbase = sWt + ci * 4 * KP;
    const float* abase = sA + ri * 8 * K;

    #pragma unroll 4
    for (int k4 = 0; k4 < KQ; k4++) {
        ulonglong2 w0 = *(const ulonglong2*)(wbase + 0 * KP + k4 * 4);
        ulonglong2 w1 = *(const ulonglong2*)(wbase + 1 * KP + k4 * 4);
        ulonglong2 w2 = *(const ulonglong2*)(wbase + 2 * KP + k4 * 4);
        ulonglong2 w3 = *(const ulonglong2*)(wbase + 3 * KP + k4 * 4);
        #pragma unroll
        for (int j = 0; j < 8; j++) {
            ulonglong2 a = *(const ulonglong2*)(abase + j * K + k4 * 4);
            fma2(acc[j][0], a.x, w0.x); fma2(acc[j][0], a.y, w0.y);
            fma2(acc[j][1], a.x, w1.x); fma2(acc[j][1], a.y, w1.y);
            fma2(acc[j][2], a.x, w2.x); fma2(acc[j][2], a.y, w2.y);
            fma2(acc[j][3], a.x, w3.x); fma2(acc[j][3], a.y, w3.y);
        }
    }

    float4* C4 = (float4*)C;
    #pragma unroll
    for (int j = 0; j < 8; j++) {
        int r = r0 + ri * 8 + j;
        if (r < N_NODES) {
            float dv = g_dinv[r];
            C4[(size_t)r * 16 + ci] = make_float4(hsum2(acc[j][0]) * dv,
                                                  hsum2(acc[j][1]) * dv,
                                                  hsum2(acc[j][2]) * dv,
                                                  hsum2(acc[j][3]) * dv);
        }
    }
}

// ---------------- fused conv (layers 2,3): hout = (relu(agg(hin)+b) @ W)*dinv ---
// Aggregation goes straight into the GEMM A-tile in smem; no g_agg round trip.
__global__ void k_conv64(const float* __restrict__ hin, const float* __restrict__ W,
                         const float* __restrict__ bias, float* __restrict__ hout) {
    constexpr int K = 64, BM = 128, KQ = 16, KP = K + 4;
    extern __shared__ float smem[];
    float* sA  = smem;            // [BM][64]
    float* sWt = smem + BM * K;   // [64][68]
    __shared__ float sB[64];

    const int tid = threadIdx.x;
    const int r0 = blockIdx.x * BM;

    for (int i = tid; i < K * 64; i += 256) {
        int k = i >> 6, c = i & 63;
        sWt[c * KP + k] = W[i];
    }
    if (tid < 64) sB[tid] = bias[tid];
    __syncthreads();

    // aggregation: 16 thread-groups of 16, each group owns one node at a time
    const int grp = tid >> 4;
    const int q   = tid & 15;
    const float4* h4 = (const float4*)hin;
    const float4* sB4 = (const float4*)sB;
    float4* sA4 = (float4*)sA;
    for (int n = grp; n < BM; n += 16) {
        int node = r0 + n;
        float4 acc = make_float4(0.f, 0.f, 0.f, 0.f);
        if (node < N_NODES) {
            acc = h4[(size_t)node * 16 + q];
            int e0 = g_rowoff[node], e1 = g_rowoff[node + 1];
            for (int e = e0; e < e1; e++) {
                int s = g_csr[e];
                float4 v = h4[(size_t)s * 16 + q];
                acc.x += v.x; acc.y += v.y; acc.z += v.z; acc.w += v.w;
            }
            float dv = g_dinv[node];
            float4 b = sB4[q];
            acc.x = fmaxf(acc.x * dv + b.x, 0.f);
            acc.y = fmaxf(acc.y * dv + b.y, 0.f);
            acc.z = fmaxf(acc.z * dv + b.z, 0.f);
            acc.w = fmaxf(acc.w * dv + b.w, 0.f);
        }
        sA4[n * 16 + q] = acc;
    }
    __syncthreads();

    const int ci = tid & 15;
    const int ri = tid >> 4;
    unsigned long long acc[8][4];
    #pragma unroll
    for (int j = 0; j < 8; j++)
        #pragma unroll
        for (int c = 0; c < 4; c++) acc[j][c] = 0ULL;

    const float* wbase = sWt + ci * 4 * KP;
    const float* abase = sA + ri * 8 * K;

    #pragma unroll 4
    for (int k4 = 0; k4 < KQ; k4++) {
        ulonglong2 w0 = *(const ulonglong2*)(wbase + 0 * KP + k4 * 4);
        ulonglong2 w1 = *(const ulonglong2*)(wbase + 1 * KP + k4 * 4);
        ulonglong2 w2 = *(const ulonglong2*)(wbase + 2 * KP + k4 * 4);
        ulonglong2 w3 = *(const ulonglong2*)(wbase + 3 * KP + k4 * 4);
        #pragma unroll
        for (int j = 0; j < 8; j++) {
            ulonglong2 a = *(const ulonglong2*)(abase + j * K + k4 * 4);
            fma2(acc[j][0], a.x, w0.x); fma2(acc[j][0], a.y, w0.y);
            fma2(acc[j][1], a.x, w1.x); fma2(acc[j][1], a.y, w1.y);
            fma2(acc[j][2], a.x, w2.x); fma2(acc[j][2], a.y, w2.y);
            fma2(acc[j][3], a.x, w3.x); fma2(acc[j][3], a.y, w3.y);
        }
    }

    float4* C4 = (float4*)hout;
    #pragma unroll
    for (int j = 0; j < 8; j++) {
        int r = r0 + ri * 8 + j;
        if (r < N_NODES) {
            float dv = g_dinv[r];
            C4[(size_t)r * 16 + ci] = make_float4(hsum2(acc[j][0]) * dv,
                                                  hsum2(acc[j][1]) * dv,
                                                  hsum2(acc[j][2]) * dv,
                                                  hsum2(acc[j][3]) * dv);
        }
    }
}

// ---------------- fused aggregate + attention + pooling + linear ----------------
// 1 warp per graph, 4 warps per block. Aggregates h3 in-warp, then attention.
__global__ void k_attn(const float* __restrict__ hin,
                       const float* __restrict__ Wa, const float* __restrict__ v,
                       const float* __restrict__ Wl, const float* __restrict__ bl,
                       const float* __restrict__ b3,
                       float* __restrict__ out, float* __restrict__ lw) {
    __shared__ float sWaT[64 * 68];
    __shared__ float sWl[128 * 32];
    __shared__ float sV[64];
    __shared__ float sBl[32];
    __shared__ float sB3[64];
    __shared__ float sH[4][LEADS * 64];
    __shared__ float sScore[4][LEADS];
    __shared__ float sPool[4][128];

    int tid = threadIdx.x;
    for (int i = tid; i < 4096; i += 128) {
        int k = i >> 6, c = i & 63;
        sWaT[c * 68 + k] = Wa[i];
        sWl[i] = Wl[i];
    }
    if (tid < 64) { sV[tid] = v[tid]; sB3[tid] = b3[tid]; }
    if (tid < 32) sBl[tid] = bl[tid];
    __syncthreads();

    int w = tid >> 5, lane = tid & 31;
    int g = blockIdx.x * 4 + w;
    if (g >= NUM_GRAPHS) return;

    float* hs = sH[w];
    const float4* h4 = (const float4*)hin;
    const float4* b34 = (const float4*)sB3;
    float4* hs4 = (float4*)hs;
    const int q  = lane & 15;
    const int eo = lane >> 4;

    // aggregate 12 leads: two half-warps process 2 edges per iteration
    #pragma unroll
    for (int l = 0; l < LEADS; l++) {
        int node = g * LEADS + l;
        float4 acc = make_float4(0.f, 0.f, 0.f, 0.f);
        if (eo == 0) acc = h4[(size_t)node * 16 + q];
        int e0 = g_rowoff[node], e1 = g_rowoff[node + 1];
        for (int e = e0 + eo; e < e1; e += 2) {
            float4 vv = h4[(size_t)g_csr[e] * 16 + q];
            acc.x += vv.x; acc.y += vv.y; acc.z += vv.z; acc.w += vv.w;
        }
        acc.x += __shfl_xor_sync(0xffffffff, acc.x, 16);
        acc.y += __shfl_xor_sync(0xffffffff, acc.y, 16);
        acc.z += __shfl_xor_sync(0xffffffff, acc.z, 16);
        acc.w += __shfl_xor_sync(0xffffffff, acc.w, 16);
        if (eo == 0) {
            float dv = g_dinv[node];
            float4 b = b34[q];
            acc.x = fmaxf(acc.x * dv + b.x, 0.f);
            acc.y = fmaxf(acc.y * dv + b.y, 0.f);
            acc.z = fmaxf(acc.z * dv + b.z, 0.f);
            acc.w = fmaxf(acc.w * dv + b.w, 0.f);
            hs4[l * 16 + q] = acc;
        }
    }
    __syncwarp();

    // energy = tanh(h @ Wa); lane owns output cols (lane, lane+32), k packed x2
    unsigned long long e0a[LEADS], e1a[LEADS];
    #pragma unroll
    for (int l = 0; l < LEADS; l++) { e0a[l] = 0ULL; e1a[l] = 0ULL; }
    const float* w0base = sWaT + lane * 68;
    const float* w1base = sWaT + (lane + 32) * 68;
    #pragma unroll 4
    for (int k4 = 0; k4 < 16; k4++) {
        ulonglong2 w0 = *(const ulonglong2*)(w0base + k4 * 4);
        ulonglong2 w1 = *(const ulonglong2*)(w1base + k4 * 4);
        #pragma unroll
        for (int l = 0; l < LEADS; l++) {
            ulonglong2 a = *(const ulonglong2*)(hs + l * 64 + k4 * 4);
            fma2(e0a[l], a.x, w0.x); fma2(e0a[l], a.y, w0.y);
            fma2(e1a[l], a.x, w1.x); fma2(e1a[l], a.y, w1.y);
        }
    }
    float v0 = sV[lane], v1 = sV[lane + 32];
    #pragma unroll
    for (int l = 0; l < LEADS; l++) {
        float s = tanhf(hsum2(e0a[l])) * v0 + tanhf(hsum2(e1a[l])) * v1;
        #pragma unroll
        for (int o = 16; o > 0; o >>= 1) s += __shfl_xor_sync(0xffffffff, s, o);
        if (lane == 0) sScore[w][l] = s;
    }
    __syncwarp();

    float sc[LEADS];
    #pragma unroll
    for (int l = 0; l < LEADS; l++) sc[l] = sScore[w][l];
    float m = sc[0];
    #pragma unroll
    for (int l = 1; l < LEADS; l++) m = fmaxf(m, sc[l]);
    float sum = 0.f;
    #pragma unroll
    for (int l = 0; l < LEADS; l++) { sc[l] = expf(sc[l] - m); sum += sc[l]; }
    float inv = 1.f / sum;
    #pragma unroll
    for (int l = 0; l < LEADS; l++) sc[l] *= inv;
    if (lane < LEADS) lw[(size_t)g * LEADS + lane] = sc[lane];

    #pragma unroll
    for (int half = 0; half < 2; half++) {
        int f = lane + 32 * half;
        float mx = -1e30f, sm = 0.f;
        #pragma unroll
        for (int l = 0; l < LEADS; l++) {
            float val = hs[l * 64 + f] * sc[l];
            mx = fmaxf(mx, val);
            sm += val;
        }
        sPool[w][f] = mx;
        sPool[w][64 + f] = sm * (1.f / 12.f);
    }
    __syncwarp();

    float acc = sBl[lane];
    #pragma unroll 16
    for (int f = 0; f < 128; f++) acc += sPool[w][f] * sWl[f * 32 + lane];
    out[(size_t)g * 32 + lane] = fmaxf(acc, 0.f);
}

// ---------------- launch --------------------------------------------------------
extern "C" void kernel_launch(void* const* d_in, const int* in_sizes, int n_in,
                              void* d_out, int out_size) {
    const float* x    = (const float*)d_in[0];
    const int*   ei   = (const int*)d_in[1];
    const int*   srcp = ei;
    const int*   dstp = ei + N_EDGES;
    const float* W1 = (const float*)d_in[3];
    const float* b1 = (const float*)d_in[4];
    const float* W2 = (const float*)d_in[5];
    const float* b2 = (const float*)d_in[6];
    const float* W3 = (const float*)d_in[7];
    const float* b3 = (const float*)d_in[8];
    const float* Wa = (const float*)d_in[9];
    const float* vv = (const float*)d_in[10];
    const float* Wl = (const float*)d_in[11];
    const float* bl = (const float*)d_in[12];

    float* out = (float*)d_out;                                  // [G,32]
    float* lw  = (float*)d_out + (size_t)NUM_GRAPHS * OUT_DIM;   // [G,12]

    float* hA; cudaGetSymbolAddress((void**)&hA, g_h);
    float* hB; cudaGetSymbolAddress((void**)&hB, g_h2);

    const int SM1 = 128 * 128 * 4 + 64 * 132 * 4;   // 99328 B
    const int SM2 = 128 * 64 * 4 + 64 * 68 * 4;     // 50176 B
    cudaFuncSetAttribute(k_gemm1,  cudaFuncAttributeMaxDynamicSharedMemorySize, SM1);
    cudaFuncSetAttribute(k_conv64, cudaFuncAttributeMaxDynamicSharedMemorySize, SM2);

    const int T = 256;
    const int gN = (N_NODES + T - 1) / T;
    const int gE = (N_EDGES + T - 1) / T;

    k_deg_zero<<<gN, T>>>();
    k_deg_count<<<gE, T>>>(dstp);
    k_dinv<<<gN, T>>>();
    k_scan1<<<SCAN_NB, 1024>>>();
    k_scan2<<<1, 1024>>>();
    k_scan3<<<(N_NODES + 1023) / 1024, 1024>>>();
    k_place<<<gE, T>>>(srcp, dstp);

    const int GRID = (N_NODES + 127) / 128;

    k_gemm1<<<GRID, 256, SM1>>>(x, W1, hA);                 // x -> hA
    k_conv64<<<GRID, 256, SM2>>>(hA, W2, b1, hB);           // agg(hA)+b1,relu @W2 -> hB
    k_conv64<<<GRID, 256, SM2>>>(hB, W3, b2, hA);           // agg(hB)+b2,relu @W3 -> hA
    k_attn<<<(NUM_GRAPHS + 3) / 4, 128>>>(hA, Wa, vv, Wl, bl, b3, out, lw);
}

// round 5
// speedup vs baseline: 1.2970x; 1.2970x over previous
#include <cuda_runtime.h>
#include <cuda_fp16.h>
#include <cuda_bf16.h>

#define N_NODES 600000
#define N_EDGES 2400000
#define LEADS 12
#define NUM_GRAPHS 50000
#define F_IN 128
#define HDIM 64
#define OUT_DIM 32

#define SCAN_NB 586   // ceil(600000/1024)

// ---------------- packed fp32x2 FMA -------------------------------------------
__device__ __forceinline__ void fma2(unsigned long long& d,
                                     unsigned long long a,
                                     unsigned long long b) {
    asm("fma.rn.f32x2 %0, %1, %2, %0;" : "+l"(d) : "l"(a), "l"(b));
}
__device__ __forceinline__ float hsum2(unsigned long long d) {
    float lo = __uint_as_float((unsigned int)(d & 0xffffffffULL));
    float hi = __uint_as_float((unsigned int)(d >> 32));
    return lo + hi;
}

// ---------------- scratch (device globals) ------------------------------------
__device__ __half g_hH[(size_t)N_NODES * HDIM];   // fp16 GEMM output (gather source)
__device__ float  g_agg[(size_t)N_NODES * HDIM];  // fp32 aggregated layer output
__device__ float  g_dinv[N_NODES];
__device__ int    g_deg[N_NODES];
__device__ int    g_rowoff[N_NODES + 1];
__device__ int    g_cursor[N_NODES];
__device__ int    g_csr[N_EDGES];
__device__ int    g_bsum[SCAN_NB];
__device__ int    g_boff[SCAN_NB];

// ---------------- degree / CSR build -------------------------------------------
__global__ void k_deg_zero() {
    int i = blockIdx.x * blockDim.x + threadIdx.x;
    if (i < N_NODES) g_deg[i] = 0;
}

__global__ void k_deg_count(const int* __restrict__ dst) {
    int e = blockIdx.x * blockDim.x + threadIdx.x;
    if (e < N_EDGES) atomicAdd(&g_deg[dst[e]], 1);
}

__global__ void k_dinv() {
    int i = blockIdx.x * blockDim.x + threadIdx.x;
    if (i < N_NODES) g_dinv[i] = rsqrtf((float)(g_deg[i] + 1));
}

__global__ void k_scan1() {
    __shared__ int sh[1024];
    int i = blockIdx.x * 1024 + threadIdx.x;
    int v = (i < N_NODES) ? g_deg[i] : 0;
    sh[threadIdx.x] = v;
    __syncthreads();
    #pragma unroll
    for (int off = 1; off < 1024; off <<= 1) {
        int t = 0;
        if (threadIdx.x >= off) t = sh[threadIdx.x - off];
        __syncthreads();
        if (threadIdx.x >= off) sh[threadIdx.x] += t;
        __syncthreads();
    }
    if (i < N_NODES) g_rowoff[i] = sh[threadIdx.x] - v;   // exclusive
    if (threadIdx.x == 1023) g_bsum[blockIdx.x] = sh[1023];
}

__global__ void k_scan2() {
    __shared__ int sh[1024];
    int v = (threadIdx.x < SCAN_NB) ? g_bsum[threadIdx.x] : 0;
    sh[threadIdx.x] = v;
    __syncthreads();
    #pragma unroll
    for (int off = 1; off < 1024; off <<= 1) {
        int t = 0;
        if (threadIdx.x >= off) t = sh[threadIdx.x - off];
        __syncthreads();
        if (threadIdx.x >= off) sh[threadIdx.x] += t;
        __syncthreads();
    }
    if (threadIdx.x < SCAN_NB) g_boff[threadIdx.x] = sh[threadIdx.x] - v;
}

__global__ void k_scan3() {
    int i = blockIdx.x * blockDim.x + threadIdx.x;
    if (i < N_NODES) {
        int ro = g_rowoff[i] + g_boff[i >> 10];
        g_rowoff[i] = ro;
        g_cursor[i] = ro;
    }
    if (i == 0) g_rowoff[N_NODES] = N_EDGES;
}

__global__ void k_place(const int* __restrict__ src, const int* __restrict__ dst) {
    int e = blockIdx.x * blockDim.x + threadIdx.x;
    if (e < N_EDGES) {
        int pos = atomicAdd(&g_cursor[dst[e]], 1);
        g_csr[pos] = src[e];
    }
}

// ---------------- GEMM: C_fp16[N,64] = (act(A)[N,K] @ W[K,64]) * dinv[row] -----
// BM=128 rows/block, 256 threads, 8x4 thread tile, fp32x2 packed FMA.
template<int K, bool ACT>
__global__ void k_gemm(const float* __restrict__ A, const float* __restrict__ W,
                       const float* __restrict__ bias, __half* __restrict__ C) {
    constexpr int BM = 128;
    constexpr int KQ = K / 4;
    constexpr int KP = K + 4;
    extern __shared__ float smem[];
    float* sA  = smem;            // [BM][K]
    float* sWt = smem + BM * K;   // [64][K+4]

    const int tid = threadIdx.x;
    const int r0 = blockIdx.x * BM;

    for (int i = tid; i < K * 64; i += 256) {
        int k = i >> 6, c = i & 63;
        sWt[c * KP + k] = W[i];
    }
    const float4* A4 = (const float4*)A;
    const float4* B4 = (const float4*)bias;
    float4* sA4 = (float4*)sA;
    for (int i = tid; i < BM * KQ; i += 256) {
        int row = i / KQ, kq = i - row * KQ;
        float4 a = make_float4(0.f, 0.f, 0.f, 0.f);
        if (r0 + row < N_NODES) a = A4[(size_t)(r0 + row) * KQ + kq];
        if (ACT) {
            float4 b = B4[kq];
            a.x = fmaxf(a.x + b.x, 0.f);
            a.y = fmaxf(a.y + b.y, 0.f);
            a.z = fmaxf(a.z + b.z, 0.f);
            a.w = fmaxf(a.w + b.w, 0.f);
        }
        sA4[i] = a;
    }
    __syncthreads();

    const int ci = tid & 15;
    const int ri = tid >> 4;
    unsigned long long acc[8][4];
    #pragma unroll
    for (int j = 0; j < 8; j++)
        #pragma unroll
        for (int c = 0; c < 4; c++) acc[j][c] = 0ULL;

    const float* wbase = sWt + ci * 4 * KP;
    const float* abase = sA + ri * 8 * K;

    #pragma unroll 4
    for (int k4 = 0; k4 < KQ; k4++) {
        ulonglong2 w0 = *(const ulonglong2*)(wbase + 0 * KP + k4 * 4);
        ulonglong2 w1 = *(const ulonglong2*)(wbase + 1 * KP + k4 * 4);
        ulonglong2 w2 = *(const ulonglong2*)(wbase + 2 * KP + k4 * 4);
        ulonglong2 w3 = *(const ulonglong2*)(wbase + 3 * KP + k4 * 4);
        #pragma unroll
        for (int j = 0; j < 8; j++) {
            ulonglong2 a = *(const ulonglong2*)(abase + j * K + k4 * 4);
            fma2(acc[j][0], a.x, w0.x); fma2(acc[j][0], a.y, w0.y);
            fma2(acc[j][1], a.x, w1.x); fma2(acc[j][1], a.y, w1.y);
            fma2(acc[j][2], a.x, w2.x); fma2(acc[j][2], a.y, w2.y);
            fma2(acc[j][3], a.x, w3.x); fma2(acc[j][3], a.y, w3.y);
        }
    }

    __half2* C2 = (__half2*)C;
    #pragma unroll
    for (int j = 0; j < 8; j++) {
        int r = r0 + ri * 8 + j;
        if (r < N_NODES) {
            float dv = g_dinv[r];
            C2[(size_t)r * 32 + ci * 2]     = __floats2half2_rn(hsum2(acc[j][0]) * dv,
                                                                hsum2(acc[j][1]) * dv);
            C2[(size_t)r * 32 + ci * 2 + 1] = __floats2half2_rn(hsum2(acc[j][2]) * dv,
                                                                hsum2(acc[j][3]) * dv);
        }
    }
}

// ---------------- CSR aggregation (fp16 gather, fp32 accumulate) ---------------
// 8 threads per node; each thread owns 8 consecutive features (one uint4 = 16B).
__global__ void k_aggregate() {
    int idx = blockIdx.x * blockDim.x + threadIdx.x;   // over N*8
    if (idx >= N_NODES * 8) return;
    int node = idx >> 3;
    int q = idx & 7;
    const uint4* h4 = (const uint4*)g_hH;   // row = 8 uint4s

    float a[8];
    uint4 r = h4[(size_t)node * 8 + q];     // self
    {
        const __half2* p = (const __half2*)&r;
        #pragma unroll
        for (int i = 0; i < 4; i++) {
            float2 f = __half22float2(p[i]);
            a[2 * i] = f.x; a[2 * i + 1] = f.y;
        }
    }
    int e0 = g_rowoff[node], e1 = g_rowoff[node + 1];
    for (int e = e0; e < e1; e++) {
        int s = __ldg(&g_csr[e]);
        uint4 rr = h4[(size_t)s * 8 + q];
        const __half2* p = (const __half2*)&rr;
        #pragma unroll
        for (int i = 0; i < 4; i++) {
            float2 f = __half22float2(p[i]);
            a[2 * i] += f.x; a[2 * i + 1] += f.y;
        }
    }
    float dv = g_dinv[node];
    #pragma unroll
    for (int i = 0; i < 8; i++) a[i] *= dv;
    float4* agg4 = (float4*)g_agg;
    agg4[(size_t)node * 16 + q * 2]     = make_float4(a[0], a[1], a[2], a[3]);
    agg4[(size_t)node * 16 + q * 2 + 1] = make_float4(a[4], a[5], a[6], a[7]);
}

// ---------------- attention + pooling + final linear ---------------------------
// 1 warp per graph, 4 warps per block. Applies relu(h + b3) on load of g_agg.
__global__ void k_attn(const float* __restrict__ Wa, const float* __restrict__ v,
                       const float* __restrict__ Wl, const float* __restrict__ bl,
                       const float* __restrict__ b3,
                       float* __restrict__ out, float* __restrict__ lw) {
    __shared__ float sWaT[64 * 68];
    __shared__ float sWl[128 * 32];
    __shared__ float sV[64];
    __shared__ float sBl[32];
    __shared__ float sB3[64];
    __shared__ float sH[4][LEADS * 64];
    __shared__ float sScore[4][LEADS];
    __shared__ float sPool[4][128];

    int tid = threadIdx.x;
    for (int i = tid; i < 4096; i += 128) {
        int k = i >> 6, c = i & 63;
        sWaT[c * 68 + k] = Wa[i];
        sWl[i] = Wl[i];
    }
    if (tid < 64) { sV[tid] = v[tid]; sB3[tid] = b3[tid]; }
    if (tid < 32) sBl[tid] = bl[tid];
    __syncthreads();

    int w = tid >> 5, lane = tid & 31;
    int g = blockIdx.x * 4 + w;
    if (g >= NUM_GRAPHS) return;

    float* hs = sH[w];
    const float4* hg4 = (const float4*)(g_agg + (size_t)g * (LEADS * 64));
    const float4* b34 = (const float4*)sB3;
    float4* hs4 = (float4*)hs;
    #pragma unroll
    for (int j = 0; j < 6; j++) {
        int id = lane + 32 * j;
        float4 hv = hg4[id];
        float4 b = b34[id & 15];
        hv.x = fmaxf(hv.x + b.x, 0.f);
        hv.y = fmaxf(hv.y + b.y, 0.f);
        hv.z = fmaxf(hv.z + b.z, 0.f);
        hv.w = fmaxf(hv.w + b.w, 0.f);
        hs4[id] = hv;
    }
    __syncwarp();

    unsigned long long e0a[LEADS], e1a[LEADS];
    #pragma unroll
    for (int l = 0; l < LEADS; l++) { e0a[l] = 0ULL; e1a[l] = 0ULL; }
    const float* w0base = sWaT + lane * 68;
    const float* w1base = sWaT + (lane + 32) * 68;
    #pragma unroll 4
    for (int k4 = 0; k4 < 16; k4++) {
        ulonglong2 w0 = *(const ulonglong2*)(w0base + k4 * 4);
        ulonglong2 w1 = *(const ulonglong2*)(w1base + k4 * 4);
        #pragma unroll
        for (int l = 0; l < LEADS; l++) {
            ulonglong2 a = *(const ulonglong2*)(hs + l * 64 + k4 * 4);
            fma2(e0a[l], a.x, w0.x); fma2(e0a[l], a.y, w0.y);
            fma2(e1a[l], a.x, w1.x); fma2(e1a[l], a.y, w1.y);
        }
    }
    float v0 = sV[lane], v1 = sV[lane + 32];
    #pragma unroll
    for (int l = 0; l < LEADS; l++) {
        float s = tanhf(hsum2(e0a[l])) * v0 + tanhf(hsum2(e1a[l])) * v1;
        #pragma unroll
        for (int o = 16; o > 0; o >>= 1) s += __shfl_xor_sync(0xffffffff, s, o);
        if (lane == 0) sScore[w][l] = s;
    }
    __syncwarp();

    float sc[LEADS];
    #pragma unroll
    for (int l = 0; l < LEADS; l++) sc[l] = sScore[w][l];
    float m = sc[0];
    #pragma unroll
    for (int l = 1; l < LEADS; l++) m = fmaxf(m, sc[l]);
    float sum = 0.f;
    #pragma unroll
    for (int l = 0; l < LEADS; l++) { sc[l] = expf(sc[l] - m); sum += sc[l]; }
    float inv = 1.f / sum;
    #pragma unroll
    for (int l = 0; l < LEADS; l++) sc[l] *= inv;
    if (lane < LEADS) lw[(size_t)g * LEADS + lane] = sc[lane];

    #pragma unroll
    for (int half = 0; half < 2; half++) {
        int f = lane + 32 * half;
        float mx = -1e30f, sm = 0.f;
        #pragma unroll
        for (int l = 0; l < LEADS; l++) {
            float val = hs[l * 64 + f] * sc[l];
            mx = fmaxf(mx, val);
            sm += val;
        }
        sPool[w][f] = mx;
        sPool[w][64 + f] = sm * (1.f / 12.f);
    }
    __syncwarp();

    float acc = sBl[lane];
    #pragma unroll 16
    for (int f = 0; f < 128; f++) acc += sPool[w][f] * sWl[f * 32 + lane];
    out[(size_t)g * 32 + lane] = fmaxf(acc, 0.f);
}

// ---------------- launch --------------------------------------------------------
extern "C" void kernel_launch(void* const* d_in, const int* in_sizes, int n_in,
                              void* d_out, int out_size) {
    const float* x    = (const float*)d_in[0];
    const int*   ei   = (const int*)d_in[1];
    const int*   srcp = ei;
    const int*   dstp = ei + N_EDGES;
    const float* W1 = (const float*)d_in[3];
    const float* b1 = (const float*)d_in[4];
    const float* W2 = (const float*)d_in[5];
    const float* b2 = (const float*)d_in[6];
    const float* W3 = (const float*)d_in[7];
    const float* b3 = (const float*)d_in[8];
    const float* Wa = (const float*)d_in[9];
    const float* vv = (const float*)d_in[10];
    const float* Wl = (const float*)d_in[11];
    const float* bl = (const float*)d_in[12];

    float* out = (float*)d_out;                                  // [G,32]
    float* lw  = (float*)d_out + (size_t)NUM_GRAPHS * OUT_DIM;   // [G,12]

    __half* hp;  cudaGetSymbolAddress((void**)&hp,  g_hH);
    float* aggp; cudaGetSymbolAddress((void**)&aggp, g_agg);

    const int SM1 = 128 * 128 * 4 + 64 * 132 * 4;   // 99328 B
    const int SM2 = 128 * 64 * 4 + 64 * 68 * 4;     // 50176 B
    cudaFuncSetAttribute(k_gemm<128, false>, cudaFuncAttributeMaxDynamicSharedMemorySize, SM1);
    cudaFuncSetAttribute(k_gemm<64, true>,  cudaFuncAttributeMaxDynamicSharedMemorySize, SM2);

    const int T = 256;
    const int gN = (N_NODES + T - 1) / T;
    const int gE = (N_EDGES + T - 1) / T;

    k_deg_zero<<<gN, T>>>();
    k_deg_count<<<gE, T>>>(dstp);
    k_dinv<<<gN, T>>>();
    k_scan1<<<SCAN_NB, 1024>>>();
    k_scan2<<<1, 1024>>>();
    k_scan3<<<(N_NODES + 1023) / 1024, 1024>>>();
    k_place<<<gE, T>>>(srcp, dstp);

    const int GEMM_GRID = (N_NODES + 127) / 128;
    const int AGG_GRID  = (N_NODES * 8 + T - 1) / T;

    k_gemm<128, false><<<GEMM_GRID, 256, SM1>>>(x, W1, nullptr, hp);
    k_aggregate<<<AGG_GRID, T>>>();
    k_gemm<64, true><<<GEMM_GRID, 256, SM2>>>(aggp, W2, b1, hp);
    k_aggregate<<<AGG_GRID, T>>>();
    k_gemm<64, true><<<GEMM_GRID, 256, SM2>>>(aggp, W3, b2, hp);
    k_aggregate<<<AGG_GRID, T>>>();

    k_attn<<<(NUM_GRAPHS + 3) / 4, 128>>>(Wa, vv, Wl, bl, b3, out, lw);
}